// round 16
// baseline (speedup 1.0000x reference)
#include <cuda_runtime.h>
#include <cuda_bf16.h>
#include <math.h>
#include <cstdint>

#define T_LEN 1024
#define BATCH 64
#define HID   512
#define G4H   2048
#define OUT_ELEMS 67108864LL           // T*B*2H
#define HID_ELEMS 131072LL             // 2L*B*H

// Scratch (allocation-free rule: __device__ globals)
__device__ float g_G[2][134217728];    // [d][T*B][4H]  precomputed x-part + biases
__device__ __nv_bfloat16 g_h_hi[2][2][32768];  // [pingpong][d][B*H] bf16-hi plane
__device__ __nv_bfloat16 g_h_lo[2][2][32768];  // [pingpong][d][B*H] bf16-lo plane
// Pre-split bf16 planes for the GEMM (X per direction, W per direction).
// Layer-1 X planes are written DIRECTLY by the layer-0 recur kernel.
__device__ __nv_bfloat16 g_x_hi[2][33554432];
__device__ __nv_bfloat16 g_x_lo[2][33554432];
__device__ __nv_bfloat16 g_w_hi[2][2097152];   // [d][L*4H*HID]
__device__ __nv_bfloat16 g_w_lo[2][2097152];
__device__ unsigned long long g_cnt2[2] = {0ull, 0ull};
__device__ unsigned long long g_flag[2][64];   // zero-initialized release flags

__device__ __forceinline__ float sigf(float x){ return 1.0f / (1.0f + expf(-x)); }

// Two-level grid barrier over 64 blocks per direction.
// Arrivals: monotonic ticket atomicAdd on cnt (proven R9 pattern).
// Release: the 64th arriver atomicMax's each block's PRIVATE flag word to the
// wave number (monotonic -> no regression hazard); every other block polls
// ONLY its own flag with an atomic RMW (strong op — weak-load poll races,
// proven R8). Removes all poller-vs-arrival and poller-vs-poller same-address
// serialization at the LTS atomic ALU.
__device__ __forceinline__ void grid_barrier_dir(int d, int bq){
    __syncthreads();
    if (threadIdx.x == 0){
        __threadfence();
        unsigned long long ticket = atomicAdd(&g_cnt2[d], 1ull);
        unsigned long long wave = ticket / 64ull + 1ull;
        if ((ticket & 63ull) == 63ull){
            __threadfence();
            #pragma unroll 8
            for (int i = 0; i < 64; i++)
                atomicMax(&g_flag[d][i], wave);
        } else {
            while (atomicAdd(&g_flag[d][bq], 0ull) < wave) { __nanosleep(32); }
        }
    }
    __syncthreads();
}

__global__ void zero_h_kernel(){
    int idx = blockIdx.x * blockDim.x + threadIdx.x;
    if (idx < 65536){
        ((uint32_t*)g_h_hi)[idx] = 0u;
        ((uint32_t*)g_h_lo)[idx] = 0u;
    }
}

// ---------------------------------------------------------------------------
// mma.sync + cp.async helpers (baseline PTX — compiles for generic compute_103)
// ---------------------------------------------------------------------------
__device__ __forceinline__ uint32_t smem_u32(const void* p){
    uint32_t a;
    asm("{ .reg .u64 t; cvta.to.shared.u64 t, %1; cvt.u32.u64 %0, t; }"
        : "=r"(a) : "l"(p));
    return a;
}
__device__ __forceinline__ void ldsm_x4(uint32_t* r, uint32_t addr){
    asm volatile("ldmatrix.sync.aligned.m8n8.x4.shared.b16 {%0,%1,%2,%3}, [%4];"
        : "=r"(r[0]), "=r"(r[1]), "=r"(r[2]), "=r"(r[3]) : "r"(addr));
}
__device__ __forceinline__ void mma16816(float* c, const uint32_t* a, const uint32_t* b){
    asm volatile(
        "mma.sync.aligned.m16n8k16.row.col.f32.bf16.bf16.f32 "
        "{%0,%1,%2,%3}, {%4,%5,%6,%7}, {%8,%9}, {%0,%1,%2,%3};"
        : "+f"(c[0]), "+f"(c[1]), "+f"(c[2]), "+f"(c[3])
        : "r"(a[0]), "r"(a[1]), "r"(a[2]), "r"(a[3]), "r"(b[0]), "r"(b[1]));
}
__device__ __forceinline__ void cp_async16(uint32_t saddr, const void* gptr){
    asm volatile("cp.async.cg.shared.global [%0], [%1], 16;"
        :: "r"(saddr), "l"(gptr) : "memory");
}
#define CP_COMMIT() asm volatile("cp.async.commit_group;" ::: "memory")
#define CP_WAIT(n)  asm volatile("cp.async.wait_group %0;" :: "n"(n) : "memory")

// Split one float into (hi, lo) bf16 pair; pack two lanes into u32s.
__device__ __forceinline__ void split2(float x0, float x1, uint32_t &hi, uint32_t &lo){
    __nv_bfloat16 h0 = __float2bfloat16_rn(x0);
    __nv_bfloat16 h1 = __float2bfloat16_rn(x1);
    float r0 = x0 - __bfloat162float(h0);
    float r1 = x1 - __bfloat162float(h1);
    __nv_bfloat16 l0 = __float2bfloat16_rn(r0);
    __nv_bfloat16 l1 = __float2bfloat16_rn(r1);
    hi = ((uint32_t)__bfloat16_as_ushort(h1) << 16) | (uint32_t)__bfloat16_as_ushort(h0);
    lo = ((uint32_t)__bfloat16_as_ushort(l1) << 16) | (uint32_t)__bfloat16_as_ushort(l0);
}

// Elementwise f32 -> (bf16 hi, bf16 lo) plane split (bandwidth-bound).
__global__ void split_plane_kernel(const float* __restrict__ src,
                                   __nv_bfloat16* __restrict__ hi,
                                   __nv_bfloat16* __restrict__ lo, int n4){
    int i = blockIdx.x * blockDim.x + threadIdx.x;
    if (i < n4){
        float4 v = ((const float4*)src)[i];
        uint32_t h0,l0,h1,l1;
        split2(v.x, v.y, h0, l0); split2(v.z, v.w, h1, l1);
        ((uint2*)hi)[i] = make_uint2(h0, h1);
        ((uint2*)lo)[i] = make_uint2(l0, l1);
    }
}

// ---------------------------------------------------------------------------
// Input-projection GEMM — cp.async 2-stage pipeline on pre-split bf16 planes.
// R14 fragment math; loop reordered to ONE __syncthreads per chunk:
//   wait(own chunk-c copies) -> sync (all warps done reading stage (c+1)&1
//   from iter c-1 AND have waited) -> issue chunk c+1 -> compute chunk c.
// ---------------------------------------------------------------------------
#define STG_BYTES 40960               // 4 tiles * 128 rows * 80B
#define AHI_OFF   0
#define ALO_OFF   10240
#define BHI_OFF   20480
#define BLO_OFF   30720

__global__ void __launch_bounds__(256, 2)
gemm_mma_kernel(int layer,
                const float* __restrict__ bxf, const float* __restrict__ bhf,
                const float* __restrict__ bxb, const float* __restrict__ bhb)
{
    extern __shared__ char smem[];
    float* bias_s = (float*)smem;                 // 128 floats
    char*  stage0 = smem + 1024;

    const int d  = blockIdx.z;
    const int n0 = blockIdx.x * 128;
    const int m0 = blockIdx.y * 128;
    const __nv_bfloat16* Xh = (layer == 0) ? g_x_hi[0] : g_x_hi[d];
    const __nv_bfloat16* Xl = (layer == 0) ? g_x_lo[0] : g_x_lo[d];
    const __nv_bfloat16* Wh = g_w_hi[d] + (size_t)layer * G4H * HID;
    const __nv_bfloat16* Wl = g_w_lo[d] + (size_t)layer * G4H * HID;
    const float* bx = (d ? bxb : bxf) + layer * G4H;
    const float* bh = (d ? bhb : bhf) + layer * G4H;
    float* Gout = g_G[d];

    const int tid  = threadIdx.x;
    const int wid  = tid >> 5;
    const int lane = tid & 31;
    const int warp_m = (wid >> 2) * 64;
    const int warp_n = (wid & 3) * 32;

    if (tid < 128) bias_s[tid] = bx[n0 + tid] + bh[n0 + tid];

    const int a_row_sel = (lane & 7) + ((lane >> 3) & 1) * 8;   // + mi*16
    const int a_kseg    = (lane >> 3) >> 1;                     // 0/1
    const int b_row4    = ((lane >> 4) << 3) + (lane & 7);      // + ni2*16
    const int b_kseg    = (lane >> 3) & 1;

    const uint32_t st_u32 = smem_u32(stage0);

    // cp.async mapping: 8 ops/thread, 2 per plane (Ahi,Alo,Bhi,Blo).
    uint32_t dsto[8];
    const __nv_bfloat16* srcp[8];
    #pragma unroll
    for (int j = 0; j < 8; j++){
        const int idx = j * 256 + tid;
        const int pl = idx >> 9, r = (idx >> 2) & 127, c = idx & 3;
        dsto[j] = st_u32 + (uint32_t)(pl * 10240 + r * 80 + c * 16);
        const __nv_bfloat16* base =
            (pl == 0) ? Xh + (size_t)(m0 + r) * HID :
            (pl == 1) ? Xl + (size_t)(m0 + r) * HID :
            (pl == 2) ? Wh + (size_t)(n0 + r) * HID :
                        Wl + (size_t)(n0 + r) * HID;
        srcp[j] = base + c * 8;
    }

    float acc[4][4][4];
    #pragma unroll
    for (int mi = 0; mi < 4; mi++)
        #pragma unroll
        for (int ni = 0; ni < 4; ni++)
            #pragma unroll
            for (int e = 0; e < 4; e++) acc[mi][ni][e] = 0.0f;

    // Prologue: stage chunk 0.
    #pragma unroll
    for (int j = 0; j < 8; j++) cp_async16(dsto[j], srcp[j]);
    CP_COMMIT();

    for (int c = 0; c < 16; c++){
        CP_WAIT(0);          // own chunk-c copies complete
        __syncthreads();     // everyone waited; stage (c+1)&1 readers done
        if (c < 15){
            const int kt = (c + 1) * 32;
            const uint32_t so = (uint32_t)((c + 1) & 1) * STG_BYTES;
            #pragma unroll
            for (int j = 0; j < 8; j++)
                cp_async16(dsto[j] + so, srcp[j] + kt);
            CP_COMMIT();
        }

        const uint32_t sb = st_u32 + (uint32_t)(c & 1) * STG_BYTES;
        #pragma unroll
        for (int kk = 0; kk < 2; kk++){
            uint32_t ahi[4][4], alo[4][4], bhi4[2][4], blo4[2][4];
            #pragma unroll
            for (int mi = 0; mi < 4; mi++){
                const uint32_t ra = sb +
                    (uint32_t)((warp_m + mi*16 + a_row_sel) * 80 + (kk*2 + a_kseg) * 16);
                ldsm_x4(ahi[mi], ra + AHI_OFF);
                ldsm_x4(alo[mi], ra + ALO_OFF);
            }
            #pragma unroll
            for (int n2 = 0; n2 < 2; n2++){
                const uint32_t rb = sb +
                    (uint32_t)((warp_n + n2*16 + b_row4) * 80 + (kk*2 + b_kseg) * 16);
                ldsm_x4(bhi4[n2], rb + BHI_OFF);
                ldsm_x4(blo4[n2], rb + BLO_OFF);
            }
            #pragma unroll
            for (int mi = 0; mi < 4; mi++)
                #pragma unroll
                for (int ni = 0; ni < 4; ni++){
                    const uint32_t* bh_f = bhi4[ni >> 1] + (ni & 1) * 2;
                    const uint32_t* bl_f = blo4[ni >> 1] + (ni & 1) * 2;
                    mma16816(acc[mi][ni], ahi[mi], bh_f);
                    mma16816(acc[mi][ni], ahi[mi], bl_f);
                    mma16816(acc[mi][ni], alo[mi], bh_f);
                }
        }
    }

    #pragma unroll
    for (int mi = 0; mi < 4; mi++){
        const int r0 = m0 + warp_m + mi*16 + (lane >> 2);
        #pragma unroll
        for (int ni = 0; ni < 4; ni++){
            const int colL = warp_n + ni*8 + (lane & 3)*2;
            const float b0v = bias_s[colL], b1v = bias_s[colL + 1];
            const size_t o0 = (size_t)r0 * G4H + n0 + colL;
            *(float2*)(Gout + o0) =
                make_float2(acc[mi][ni][0] + b0v, acc[mi][ni][1] + b1v);
            *(float2*)(Gout + o0 + (size_t)8 * G4H) =
                make_float2(acc[mi][ni][2] + b0v, acc[mi][ni][3] + b1v);
        }
    }
}

// ---------------------------------------------------------------------------
// Persistent recurrent kernel — R10-exact compute structure (frozen).
// Only the grid barrier changed this round (two-level flag barrier).
// ---------------------------------------------------------------------------
#define WROW    1040
#define WHI_OFF 0
#define WLO_OFF 33280
#define HHI_OFF 66560
#define HLO_OFF 133120
#define REC_SMEM 199680

__global__ void __launch_bounds__(256, 1)
recur_kernel(int layer, const float* __restrict__ Whh_f,
             const float* __restrict__ Whh_b, float* __restrict__ out)
{
    extern __shared__ char smem[];
    float* buf = (float*)(smem + HHI_OFF);   // alias: 32x65 floats, used post-MMA

    const int tid = threadIdx.x;
    const int bid = blockIdx.x;
    const int d  = bid >> 6;
    const int bq = bid & 63;
    const int j0 = bq << 3;
    const float* Wh = (d ? Whh_b : Whh_f) + (size_t)layer * G4H * HID;
    const float* Gm = g_G[d];

    for (int idx = tid; idx < 32 * 512; idx += 256){
        int rr = idx >> 9, k = idx & 511;
        int rg = ((rr >> 3) << 9) + j0 + (rr & 7);
        float w = Wh[(size_t)rg * HID + k];
        __nv_bfloat16 hi = __float2bfloat16_rn(w);
        __nv_bfloat16 lo = __float2bfloat16_rn(w - __bfloat162float(hi));
        *(__nv_bfloat16*)(smem + WHI_OFF + rr * WROW + k * 2) = hi;
        *(__nv_bfloat16*)(smem + WLO_OFF + rr * WROW + k * 2) = lo;
    }

    const int wid  = tid >> 5;
    const int lane = tid & 31;
    const int warp_m = (wid & 3) * 16;
    const int warp_n = (wid >> 2) * 16;
    const int a_row = (lane & 7) + ((lane >> 3) & 1) * 8;
    const int a_ks  = lane >> 4;
    const int b_row4 = ((lane >> 4) << 3) + (lane & 7);
    const int b_ks   = (lane >> 3) & 1;

    const uint32_t s32 = smem_u32(smem);
    const uint32_t a_hi_b = s32 + HHI_OFF + (uint32_t)(warp_m + a_row) * WROW + a_ks * 16;
    const uint32_t a_lo_b = s32 + HLO_OFF + (uint32_t)(warp_m + a_row) * WROW + a_ks * 16;
    const uint32_t b_hi_b = s32 + WHI_OFF + (uint32_t)(warp_n + b_row4) * WROW + b_ks * 16;
    const uint32_t b_lo_b = s32 + WLO_OFF + (uint32_t)(warp_n + b_row4) * WROW + b_ks * 16;

    const int jl = tid & 7;
    const int b0 = tid >> 3;
    float c0 = 0.0f, c1 = 0.0f;
    int p = 0;

    for (int s = 0; s < T_LEN; s++){
        const int t = d ? (T_LEN - 1 - s) : s;

        const __nv_bfloat16* hh = g_h_hi[p][d];
        const __nv_bfloat16* hl = g_h_lo[p][d];
        #pragma unroll
        for (int it = 0; it < 16; it++){
            int idx = tid + it * 256;
            uint32_t so = (uint32_t)(idx >> 6) * WROW + (uint32_t)(idx & 63) * 16;
            uint4 vh = __ldcg((const uint4*)hh + idx);
            uint4 vl = __ldcg((const uint4*)hl + idx);
            *(uint4*)(smem + HHI_OFF + so) = vh;
            *(uint4*)(smem + HLO_OFF + so) = vl;
        }
        const size_t mb0 = ((size_t)t * 64 + b0)      * G4H + j0 + jl;
        const size_t mb1 = ((size_t)t * 64 + b0 + 32) * G4H + j0 + jl;
        float ga0[4], ga1[4];
        #pragma unroll
        for (int e = 0; e < 4; e++){
            ga0[e] = __ldg(Gm + mb0 + (e << 9));
            ga1[e] = __ldg(Gm + mb1 + (e << 9));
        }
        __syncthreads();

        float accA[2][4], accB[2][4], accC[2][4];
        #pragma unroll
        for (int ni = 0; ni < 2; ni++)
            #pragma unroll
            for (int e = 0; e < 4; e++){
                accA[ni][e] = 0.0f; accB[ni][e] = 0.0f; accC[ni][e] = 0.0f;
            }

        #pragma unroll 4
        for (int ck = 0; ck < 32; ck++){
            const uint32_t off = (uint32_t)ck * 32;
            uint32_t ah[4], al[4], bh4[4], bl4[4];
            ldsm_x4(ah, a_hi_b + off);
            ldsm_x4(al, a_lo_b + off);
            ldsm_x4(bh4, b_hi_b + off);
            ldsm_x4(bl4, b_lo_b + off);
            mma16816(accA[0], ah, bh4 + 0);
            mma16816(accA[1], ah, bh4 + 2);
            mma16816(accB[0], ah, bl4 + 0);
            mma16816(accB[1], ah, bl4 + 2);
            mma16816(accC[0], al, bh4 + 0);
            mma16816(accC[1], al, bh4 + 2);
        }
        __syncthreads();

        const int er = warp_m + (lane >> 2);
        #pragma unroll
        for (int ni = 0; ni < 2; ni++){
            const int bc = warp_n + ni * 8 + (lane & 3) * 2;
            buf[bc * 65 + er]           = accA[ni][0] + accB[ni][0] + accC[ni][0];
            buf[(bc + 1) * 65 + er]     = accA[ni][1] + accB[ni][1] + accC[ni][1];
            buf[bc * 65 + er + 8]       = accA[ni][2] + accB[ni][2] + accC[ni][2];
            buf[(bc + 1) * 65 + er + 8] = accA[ni][3] + accB[ni][3] + accC[ni][3];
        }
        __syncthreads();

        float gt0[4], gt1[4];
        #pragma unroll
        for (int e = 0; e < 4; e++){
            const int rb = (e * 8 + jl) * 65;
            gt0[e] = ga0[e] + buf[rb + b0];
            gt1[e] = ga1[e] + buf[rb + b0 + 32];
        }
        c0 = sigf(gt0[1]) * c0 + sigf(gt0[0]) * tanhf(gt0[2]);
        float h0 = sigf(gt0[3]) * tanhf(c0);
        c1 = sigf(gt1[1]) * c1 + sigf(gt1[0]) * tanhf(gt1[2]);
        float h1 = sigf(gt1[3]) * tanhf(c1);

        // Split h once; feed both the h ping-pong planes and (layer 0) the
        // layer-1 X planes (bitwise-identical to the old split kernels).
        const int pn = p ^ 1;
        __nv_bfloat16 h0h = __float2bfloat16_rn(h0);
        __nv_bfloat16 h0l = __float2bfloat16_rn(h0 - __bfloat162float(h0h));
        __nv_bfloat16 h1h = __float2bfloat16_rn(h1);
        __nv_bfloat16 h1l = __float2bfloat16_rn(h1 - __bfloat162float(h1h));
        {
            const int i0 = (b0 << 9) + j0 + jl;
            const int i1 = ((b0 + 32) << 9) + j0 + jl;
            g_h_hi[pn][d][i0] = h0h;  g_h_lo[pn][d][i0] = h0l;
            g_h_hi[pn][d][i1] = h1h;  g_h_lo[pn][d][i1] = h1l;
        }

        if (layer == 0){
            const size_t o0 = ((size_t)t*64 + b0)      * HID + j0 + jl;
            const size_t o1 = ((size_t)t*64 + b0 + 32) * HID + j0 + jl;
            g_x_hi[d][o0] = h0h;  g_x_lo[d][o0] = h0l;
            g_x_hi[d][o1] = h1h;  g_x_lo[d][o1] = h1l;
        } else {
            out[(size_t)t*65536 + b0*1024        + (d << 9) + j0 + jl] = h0;
            out[(size_t)t*65536 + (b0+32)*1024   + (d << 9) + j0 + jl] = h1;
        }
        if (s == T_LEN - 1){
            const int row = d*2 + layer;
            size_t hoff = OUT_ELEMS + (size_t)(row*64 + b0) * HID + j0 + jl;
            out[hoff]                           = h0;
            out[hoff + (32 << 9)]               = h1;
            out[hoff + HID_ELEMS]               = c0;
            out[hoff + HID_ELEMS + (32 << 9)]   = c1;
        }
        grid_barrier_dir(d, bq);
        p = pn;
    }
}

// ---------------------------------------------------------------------------
extern "C" void kernel_launch(void* const* d_in, const int* in_sizes, int n_in,
                              void* d_out, int out_size)
{
    const float* x     = (const float*)d_in[0];
    const float* Wxh_f = (const float*)d_in[1];
    const float* bxh_f = (const float*)d_in[2];
    const float* Whh_f = (const float*)d_in[3];
    const float* bhh_f = (const float*)d_in[4];
    const float* Wxh_b = (const float*)d_in[5];
    const float* bxh_b = (const float*)d_in[6];
    const float* Whh_b = (const float*)d_in[7];
    const float* bhh_b = (const float*)d_in[8];
    float* out = (float*)d_out;

    const int gemm_smem = 1024 + 2 * STG_BYTES;                   // 82944 B
    cudaFuncSetAttribute(gemm_mma_kernel,
                         cudaFuncAttributeMaxDynamicSharedMemorySize, gemm_smem);
    cudaFuncSetAttribute(recur_kernel,
                         cudaFuncAttributeMaxDynamicSharedMemorySize, REC_SMEM);

    // Resolve device-symbol addresses (host-side, cheap, not allocation).
    void* p_xhi; cudaGetSymbolAddress(&p_xhi, g_x_hi);
    void* p_xlo; cudaGetSymbolAddress(&p_xlo, g_x_lo);
    void* p_whi; cudaGetSymbolAddress(&p_whi, g_w_hi);
    void* p_wlo; cudaGetSymbolAddress(&p_wlo, g_w_lo);
    __nv_bfloat16* xhi = (__nv_bfloat16*)p_xhi;
    __nv_bfloat16* xlo = (__nv_bfloat16*)p_xlo;
    __nv_bfloat16* whi = (__nv_bfloat16*)p_whi;
    __nv_bfloat16* wlo = (__nv_bfloat16*)p_wlo;

    // W planes: Wxh_f -> d=0 section, Wxh_b -> d=1 section (2097152 elems each).
    split_plane_kernel<<<2048, 256>>>(Wxh_f, whi,            wlo,            524288);
    split_plane_kernel<<<2048, 256>>>(Wxh_b, whi + 2097152,  wlo + 2097152,  524288);
    // Layer-0 X planes (shared by both directions).
    split_plane_kernel<<<32768, 256>>>(x, xhi, xlo, 8388608);

    for (int l = 0; l < 2; l++){
        gemm_mma_kernel<<<dim3(16, 512, 2), 256, gemm_smem>>>(l, bxh_f, bhh_f, bxh_b, bhh_b);
        zero_h_kernel<<<512, 256>>>();
        recur_kernel<<<128, 256, REC_SMEM>>>(l, Whh_f, Whh_b, out);
    }
}

// round 17
// speedup vs baseline: 1.3839x; 1.3839x over previous
#include <cuda_runtime.h>
#include <cuda_bf16.h>
#include <math.h>
#include <cstdint>

#define T_LEN 1024
#define BATCH 64
#define HID   512
#define G4H   2048
#define OUT_ELEMS 67108864LL           // T*B*2H
#define HID_ELEMS 131072LL             // 2L*B*H

// Scratch (allocation-free rule: __device__ globals)
__device__ float g_G[2][134217728];    // [d][T*B][4H]  precomputed x-part + biases
__device__ __nv_bfloat16 g_h_hi[2][2][32768];  // [pingpong][d][B*H] bf16-hi plane
__device__ __nv_bfloat16 g_h_lo[2][2][32768];  // [pingpong][d][B*H] bf16-lo plane
// Pre-split bf16 planes for the GEMM (X per direction, W per direction).
// Layer-1 X planes are written DIRECTLY by the layer-0 recur kernel.
__device__ __nv_bfloat16 g_x_hi[2][33554432];
__device__ __nv_bfloat16 g_x_lo[2][33554432];
__device__ __nv_bfloat16 g_w_hi[2][2097152];   // [d][L*4H*HID]
__device__ __nv_bfloat16 g_w_lo[2][2097152];
__device__ unsigned long long g_bar2[2] = {0ull, 0ull};

__device__ __forceinline__ float sigf(float x){ return 1.0f / (1.0f + expf(-x)); }

// Per-direction monotonic-ticket barrier over 64 blocks — R15 form (BEST).
// Release: stores(all) -> __syncthreads -> tid-0 __threadfence -> arrival
// atomic. Poll: atomicAdd RMW on the shared counter + nanosleep.
// CLOSED EXPERIMENTS: weak-load poll races (R8); acquire-load poll slower
// (R11); per-block flag fan-out much slower (R16 — 64 serialized same-line
// release RMWs + extra L2 hop on the critical path). Do not touch.
__device__ __forceinline__ void grid_barrier_dir(int d){
    __syncthreads();
    if (threadIdx.x == 0){
        __threadfence();
        unsigned long long ticket = atomicAdd(&g_bar2[d], 1ull);
        unsigned long long target = (ticket / 64ull + 1ull) * 64ull;
        while (atomicAdd(&g_bar2[d], 0ull) < target) { __nanosleep(32); }
    }
    __syncthreads();
}

__global__ void zero_h_kernel(){
    int idx = blockIdx.x * blockDim.x + threadIdx.x;
    if (idx < 65536){
        ((uint32_t*)g_h_hi)[idx] = 0u;
        ((uint32_t*)g_h_lo)[idx] = 0u;
    }
}

// ---------------------------------------------------------------------------
// mma.sync + cp.async helpers (baseline PTX — compiles for generic compute_103)
// ---------------------------------------------------------------------------
__device__ __forceinline__ uint32_t smem_u32(const void* p){
    uint32_t a;
    asm("{ .reg .u64 t; cvta.to.shared.u64 t, %1; cvt.u32.u64 %0, t; }"
        : "=r"(a) : "l"(p));
    return a;
}
__device__ __forceinline__ void ldsm_x4(uint32_t* r, uint32_t addr){
    asm volatile("ldmatrix.sync.aligned.m8n8.x4.shared.b16 {%0,%1,%2,%3}, [%4];"
        : "=r"(r[0]), "=r"(r[1]), "=r"(r[2]), "=r"(r[3]) : "r"(addr));
}
__device__ __forceinline__ void mma16816(float* c, const uint32_t* a, const uint32_t* b){
    asm volatile(
        "mma.sync.aligned.m16n8k16.row.col.f32.bf16.bf16.f32 "
        "{%0,%1,%2,%3}, {%4,%5,%6,%7}, {%8,%9}, {%0,%1,%2,%3};"
        : "+f"(c[0]), "+f"(c[1]), "+f"(c[2]), "+f"(c[3])
        : "r"(a[0]), "r"(a[1]), "r"(a[2]), "r"(a[3]), "r"(b[0]), "r"(b[1]));
}
__device__ __forceinline__ void cp_async16(uint32_t saddr, const void* gptr){
    asm volatile("cp.async.cg.shared.global [%0], [%1], 16;"
        :: "r"(saddr), "l"(gptr) : "memory");
}
#define CP_COMMIT() asm volatile("cp.async.commit_group;" ::: "memory")
#define CP_WAIT(n)  asm volatile("cp.async.wait_group %0;" :: "n"(n) : "memory")

// Split one float into (hi, lo) bf16 pair; pack two lanes into u32s.
__device__ __forceinline__ void split2(float x0, float x1, uint32_t &hi, uint32_t &lo){
    __nv_bfloat16 h0 = __float2bfloat16_rn(x0);
    __nv_bfloat16 h1 = __float2bfloat16_rn(x1);
    float r0 = x0 - __bfloat162float(h0);
    float r1 = x1 - __bfloat162float(h1);
    __nv_bfloat16 l0 = __float2bfloat16_rn(r0);
    __nv_bfloat16 l1 = __float2bfloat16_rn(r1);
    hi = ((uint32_t)__bfloat16_as_ushort(h1) << 16) | (uint32_t)__bfloat16_as_ushort(h0);
    lo = ((uint32_t)__bfloat16_as_ushort(l1) << 16) | (uint32_t)__bfloat16_as_ushort(l0);
}

// Elementwise f32 -> (bf16 hi, bf16 lo) plane split (bandwidth-bound).
__global__ void split_plane_kernel(const float* __restrict__ src,
                                   __nv_bfloat16* __restrict__ hi,
                                   __nv_bfloat16* __restrict__ lo, int n4){
    int i = blockIdx.x * blockDim.x + threadIdx.x;
    if (i < n4){
        float4 v = ((const float4*)src)[i];
        uint32_t h0,l0,h1,l1;
        split2(v.x, v.y, h0, l0); split2(v.z, v.w, h1, l1);
        ((uint2*)hi)[i] = make_uint2(h0, h1);
        ((uint2*)lo)[i] = make_uint2(l0, l1);
    }
}

// ---------------------------------------------------------------------------
// Input-projection GEMM — cp.async 2-stage pipeline on pre-split bf16 planes.
// R16 single-sync loop (validated: 2.04us, tensor 66.5%):
//   wait(own chunk-c copies) -> sync -> issue chunk c+1 -> compute chunk c.
// ---------------------------------------------------------------------------
#define STG_BYTES 40960               // 4 tiles * 128 rows * 80B
#define AHI_OFF   0
#define ALO_OFF   10240
#define BHI_OFF   20480
#define BLO_OFF   30720

__global__ void __launch_bounds__(256, 2)
gemm_mma_kernel(int layer,
                const float* __restrict__ bxf, const float* __restrict__ bhf,
                const float* __restrict__ bxb, const float* __restrict__ bhb)
{
    extern __shared__ char smem[];
    float* bias_s = (float*)smem;                 // 128 floats
    char*  stage0 = smem + 1024;

    const int d  = blockIdx.z;
    const int n0 = blockIdx.x * 128;
    const int m0 = blockIdx.y * 128;
    const __nv_bfloat16* Xh = (layer == 0) ? g_x_hi[0] : g_x_hi[d];
    const __nv_bfloat16* Xl = (layer == 0) ? g_x_lo[0] : g_x_lo[d];
    const __nv_bfloat16* Wh = g_w_hi[d] + (size_t)layer * G4H * HID;
    const __nv_bfloat16* Wl = g_w_lo[d] + (size_t)layer * G4H * HID;
    const float* bx = (d ? bxb : bxf) + layer * G4H;
    const float* bh = (d ? bhb : bhf) + layer * G4H;
    float* Gout = g_G[d];

    const int tid  = threadIdx.x;
    const int wid  = tid >> 5;
    const int lane = tid & 31;
    const int warp_m = (wid >> 2) * 64;
    const int warp_n = (wid & 3) * 32;

    if (tid < 128) bias_s[tid] = bx[n0 + tid] + bh[n0 + tid];

    const int a_row_sel = (lane & 7) + ((lane >> 3) & 1) * 8;   // + mi*16
    const int a_kseg    = (lane >> 3) >> 1;                     // 0/1
    const int b_row4    = ((lane >> 4) << 3) + (lane & 7);      // + ni2*16
    const int b_kseg    = (lane >> 3) & 1;

    const uint32_t st_u32 = smem_u32(stage0);

    // cp.async mapping: 8 ops/thread, 2 per plane (Ahi,Alo,Bhi,Blo).
    uint32_t dsto[8];
    const __nv_bfloat16* srcp[8];
    #pragma unroll
    for (int j = 0; j < 8; j++){
        const int idx = j * 256 + tid;
        const int pl = idx >> 9, r = (idx >> 2) & 127, c = idx & 3;
        dsto[j] = st_u32 + (uint32_t)(pl * 10240 + r * 80 + c * 16);
        const __nv_bfloat16* base =
            (pl == 0) ? Xh + (size_t)(m0 + r) * HID :
            (pl == 1) ? Xl + (size_t)(m0 + r) * HID :
            (pl == 2) ? Wh + (size_t)(n0 + r) * HID :
                        Wl + (size_t)(n0 + r) * HID;
        srcp[j] = base + c * 8;
    }

    float acc[4][4][4];
    #pragma unroll
    for (int mi = 0; mi < 4; mi++)
        #pragma unroll
        for (int ni = 0; ni < 4; ni++)
            #pragma unroll
            for (int e = 0; e < 4; e++) acc[mi][ni][e] = 0.0f;

    // Prologue: stage chunk 0.
    #pragma unroll
    for (int j = 0; j < 8; j++) cp_async16(dsto[j], srcp[j]);
    CP_COMMIT();

    for (int c = 0; c < 16; c++){
        CP_WAIT(0);          // own chunk-c copies complete
        __syncthreads();     // everyone waited; stage (c+1)&1 readers done
        if (c < 15){
            const int kt = (c + 1) * 32;
            const uint32_t so = (uint32_t)((c + 1) & 1) * STG_BYTES;
            #pragma unroll
            for (int j = 0; j < 8; j++)
                cp_async16(dsto[j] + so, srcp[j] + kt);
            CP_COMMIT();
        }

        const uint32_t sb = st_u32 + (uint32_t)(c & 1) * STG_BYTES;
        #pragma unroll
        for (int kk = 0; kk < 2; kk++){
            uint32_t ahi[4][4], alo[4][4], bhi4[2][4], blo4[2][4];
            #pragma unroll
            for (int mi = 0; mi < 4; mi++){
                const uint32_t ra = sb +
                    (uint32_t)((warp_m + mi*16 + a_row_sel) * 80 + (kk*2 + a_kseg) * 16);
                ldsm_x4(ahi[mi], ra + AHI_OFF);
                ldsm_x4(alo[mi], ra + ALO_OFF);
            }
            #pragma unroll
            for (int n2 = 0; n2 < 2; n2++){
                const uint32_t rb = sb +
                    (uint32_t)((warp_n + n2*16 + b_row4) * 80 + (kk*2 + b_kseg) * 16);
                ldsm_x4(bhi4[n2], rb + BHI_OFF);
                ldsm_x4(blo4[n2], rb + BLO_OFF);
            }
            #pragma unroll
            for (int mi = 0; mi < 4; mi++)
                #pragma unroll
                for (int ni = 0; ni < 4; ni++){
                    const uint32_t* bh_f = bhi4[ni >> 1] + (ni & 1) * 2;
                    const uint32_t* bl_f = blo4[ni >> 1] + (ni & 1) * 2;
                    mma16816(acc[mi][ni], ahi[mi], bh_f);
                    mma16816(acc[mi][ni], ahi[mi], bl_f);
                    mma16816(acc[mi][ni], alo[mi], bh_f);
                }
        }
    }

    #pragma unroll
    for (int mi = 0; mi < 4; mi++){
        const int r0 = m0 + warp_m + mi*16 + (lane >> 2);
        #pragma unroll
        for (int ni = 0; ni < 4; ni++){
            const int colL = warp_n + ni*8 + (lane & 3)*2;
            const float b0v = bias_s[colL], b1v = bias_s[colL + 1];
            const size_t o0 = (size_t)r0 * G4H + n0 + colL;
            *(float2*)(Gout + o0) =
                make_float2(acc[mi][ni][0] + b0v, acc[mi][ni][1] + b1v);
            *(float2*)(Gout + o0 + (size_t)8 * G4H) =
                make_float2(acc[mi][ni][2] + b0v, acc[mi][ni][3] + b1v);
        }
    }
}

// ---------------------------------------------------------------------------
// Persistent recurrent kernel — R10-exact compute structure (frozen),
// R15 barrier, fused layer-0 X-plane output.
// ---------------------------------------------------------------------------
#define WROW    1040
#define WHI_OFF 0
#define WLO_OFF 33280
#define HHI_OFF 66560
#define HLO_OFF 133120
#define REC_SMEM 199680

__global__ void __launch_bounds__(256, 1)
recur_kernel(int layer, const float* __restrict__ Whh_f,
             const float* __restrict__ Whh_b, float* __restrict__ out)
{
    extern __shared__ char smem[];
    float* buf = (float*)(smem + HHI_OFF);   // alias: 32x65 floats, used post-MMA

    const int tid = threadIdx.x;
    const int bid = blockIdx.x;
    const int d  = bid >> 6;
    const int j0 = (bid & 63) << 3;
    const float* Wh = (d ? Whh_b : Whh_f) + (size_t)layer * G4H * HID;
    const float* Gm = g_G[d];

    for (int idx = tid; idx < 32 * 512; idx += 256){
        int rr = idx >> 9, k = idx & 511;
        int rg = ((rr >> 3) << 9) + j0 + (rr & 7);
        float w = Wh[(size_t)rg * HID + k];
        __nv_bfloat16 hi = __float2bfloat16_rn(w);
        __nv_bfloat16 lo = __float2bfloat16_rn(w - __bfloat162float(hi));
        *(__nv_bfloat16*)(smem + WHI_OFF + rr * WROW + k * 2) = hi;
        *(__nv_bfloat16*)(smem + WLO_OFF + rr * WROW + k * 2) = lo;
    }

    const int wid  = tid >> 5;
    const int lane = tid & 31;
    const int warp_m = (wid & 3) * 16;
    const int warp_n = (wid >> 2) * 16;
    const int a_row = (lane & 7) + ((lane >> 3) & 1) * 8;
    const int a_ks  = lane >> 4;
    const int b_row4 = ((lane >> 4) << 3) + (lane & 7);
    const int b_ks   = (lane >> 3) & 1;

    const uint32_t s32 = smem_u32(smem);
    const uint32_t a_hi_b = s32 + HHI_OFF + (uint32_t)(warp_m + a_row) * WROW + a_ks * 16;
    const uint32_t a_lo_b = s32 + HLO_OFF + (uint32_t)(warp_m + a_row) * WROW + a_ks * 16;
    const uint32_t b_hi_b = s32 + WHI_OFF + (uint32_t)(warp_n + b_row4) * WROW + b_ks * 16;
    const uint32_t b_lo_b = s32 + WLO_OFF + (uint32_t)(warp_n + b_row4) * WROW + b_ks * 16;

    const int jl = tid & 7;
    const int b0 = tid >> 3;
    float c0 = 0.0f, c1 = 0.0f;
    int p = 0;

    for (int s = 0; s < T_LEN; s++){
        const int t = d ? (T_LEN - 1 - s) : s;

        const __nv_bfloat16* hh = g_h_hi[p][d];
        const __nv_bfloat16* hl = g_h_lo[p][d];
        #pragma unroll
        for (int it = 0; it < 16; it++){
            int idx = tid + it * 256;
            uint32_t so = (uint32_t)(idx >> 6) * WROW + (uint32_t)(idx & 63) * 16;
            uint4 vh = __ldcg((const uint4*)hh + idx);
            uint4 vl = __ldcg((const uint4*)hl + idx);
            *(uint4*)(smem + HHI_OFF + so) = vh;
            *(uint4*)(smem + HLO_OFF + so) = vl;
        }
        const size_t mb0 = ((size_t)t * 64 + b0)      * G4H + j0 + jl;
        const size_t mb1 = ((size_t)t * 64 + b0 + 32) * G4H + j0 + jl;
        float ga0[4], ga1[4];
        #pragma unroll
        for (int e = 0; e < 4; e++){
            ga0[e] = __ldg(Gm + mb0 + (e << 9));
            ga1[e] = __ldg(Gm + mb1 + (e << 9));
        }
        __syncthreads();

        float accA[2][4], accB[2][4], accC[2][4];
        #pragma unroll
        for (int ni = 0; ni < 2; ni++)
            #pragma unroll
            for (int e = 0; e < 4; e++){
                accA[ni][e] = 0.0f; accB[ni][e] = 0.0f; accC[ni][e] = 0.0f;
            }

        #pragma unroll 4
        for (int ck = 0; ck < 32; ck++){
            const uint32_t off = (uint32_t)ck * 32;
            uint32_t ah[4], al[4], bh4[4], bl4[4];
            ldsm_x4(ah, a_hi_b + off);
            ldsm_x4(al, a_lo_b + off);
            ldsm_x4(bh4, b_hi_b + off);
            ldsm_x4(bl4, b_lo_b + off);
            mma16816(accA[0], ah, bh4 + 0);
            mma16816(accA[1], ah, bh4 + 2);
            mma16816(accB[0], ah, bl4 + 0);
            mma16816(accB[1], ah, bl4 + 2);
            mma16816(accC[0], al, bh4 + 0);
            mma16816(accC[1], al, bh4 + 2);
        }
        __syncthreads();

        const int er = warp_m + (lane >> 2);
        #pragma unroll
        for (int ni = 0; ni < 2; ni++){
            const int bc = warp_n + ni * 8 + (lane & 3) * 2;
            buf[bc * 65 + er]           = accA[ni][0] + accB[ni][0] + accC[ni][0];
            buf[(bc + 1) * 65 + er]     = accA[ni][1] + accB[ni][1] + accC[ni][1];
            buf[bc * 65 + er + 8]       = accA[ni][2] + accB[ni][2] + accC[ni][2];
            buf[(bc + 1) * 65 + er + 8] = accA[ni][3] + accB[ni][3] + accC[ni][3];
        }
        __syncthreads();

        float gt0[4], gt1[4];
        #pragma unroll
        for (int e = 0; e < 4; e++){
            const int rb = (e * 8 + jl) * 65;
            gt0[e] = ga0[e] + buf[rb + b0];
            gt1[e] = ga1[e] + buf[rb + b0 + 32];
        }
        c0 = sigf(gt0[1]) * c0 + sigf(gt0[0]) * tanhf(gt0[2]);
        float h0 = sigf(gt0[3]) * tanhf(c0);
        c1 = sigf(gt1[1]) * c1 + sigf(gt1[0]) * tanhf(gt1[2]);
        float h1 = sigf(gt1[3]) * tanhf(c1);

        // Split h once; feed both the h ping-pong planes and (layer 0) the
        // layer-1 X planes (bitwise-identical to the old split kernels).
        const int pn = p ^ 1;
        __nv_bfloat16 h0h = __float2bfloat16_rn(h0);
        __nv_bfloat16 h0l = __float2bfloat16_rn(h0 - __bfloat162float(h0h));
        __nv_bfloat16 h1h = __float2bfloat16_rn(h1);
        __nv_bfloat16 h1l = __float2bfloat16_rn(h1 - __bfloat162float(h1h));
        {
            const int i0 = (b0 << 9) + j0 + jl;
            const int i1 = ((b0 + 32) << 9) + j0 + jl;
            g_h_hi[pn][d][i0] = h0h;  g_h_lo[pn][d][i0] = h0l;
            g_h_hi[pn][d][i1] = h1h;  g_h_lo[pn][d][i1] = h1l;
        }

        if (layer == 0){
            const size_t o0 = ((size_t)t*64 + b0)      * HID + j0 + jl;
            const size_t o1 = ((size_t)t*64 + b0 + 32) * HID + j0 + jl;
            g_x_hi[d][o0] = h0h;  g_x_lo[d][o0] = h0l;
            g_x_hi[d][o1] = h1h;  g_x_lo[d][o1] = h1l;
        } else {
            out[(size_t)t*65536 + b0*1024        + (d << 9) + j0 + jl] = h0;
            out[(size_t)t*65536 + (b0+32)*1024   + (d << 9) + j0 + jl] = h1;
        }
        if (s == T_LEN - 1){
            const int row = d*2 + layer;
            size_t hoff = OUT_ELEMS + (size_t)(row*64 + b0) * HID + j0 + jl;
            out[hoff]                           = h0;
            out[hoff + (32 << 9)]               = h1;
            out[hoff + HID_ELEMS]               = c0;
            out[hoff + HID_ELEMS + (32 << 9)]   = c1;
        }
        grid_barrier_dir(d);
        p = pn;
    }
}

// ---------------------------------------------------------------------------
extern "C" void kernel_launch(void* const* d_in, const int* in_sizes, int n_in,
                              void* d_out, int out_size)
{
    const float* x     = (const float*)d_in[0];
    const float* Wxh_f = (const float*)d_in[1];
    const float* bxh_f = (const float*)d_in[2];
    const float* Whh_f = (const float*)d_in[3];
    const float* bhh_f = (const float*)d_in[4];
    const float* Wxh_b = (const float*)d_in[5];
    const float* bxh_b = (const float*)d_in[6];
    const float* Whh_b = (const float*)d_in[7];
    const float* bhh_b = (const float*)d_in[8];
    float* out = (float*)d_out;

    const int gemm_smem = 1024 + 2 * STG_BYTES;                   // 82944 B
    cudaFuncSetAttribute(gemm_mma_kernel,
                         cudaFuncAttributeMaxDynamicSharedMemorySize, gemm_smem);
    cudaFuncSetAttribute(recur_kernel,
                         cudaFuncAttributeMaxDynamicSharedMemorySize, REC_SMEM);

    // Resolve device-symbol addresses (host-side, cheap, not allocation).
    void* p_xhi; cudaGetSymbolAddress(&p_xhi, g_x_hi);
    void* p_xlo; cudaGetSymbolAddress(&p_xlo, g_x_lo);
    void* p_whi; cudaGetSymbolAddress(&p_whi, g_w_hi);
    void* p_wlo; cudaGetSymbolAddress(&p_wlo, g_w_lo);
    __nv_bfloat16* xhi = (__nv_bfloat16*)p_xhi;
    __nv_bfloat16* xlo = (__nv_bfloat16*)p_xlo;
    __nv_bfloat16* whi = (__nv_bfloat16*)p_whi;
    __nv_bfloat16* wlo = (__nv_bfloat16*)p_wlo;

    // W planes: Wxh_f -> d=0 section, Wxh_b -> d=1 section (2097152 elems each).
    split_plane_kernel<<<2048, 256>>>(Wxh_f, whi,            wlo,            524288);
    split_plane_kernel<<<2048, 256>>>(Wxh_b, whi + 2097152,  wlo + 2097152,  524288);
    // Layer-0 X planes (shared by both directions).
    split_plane_kernel<<<32768, 256>>>(x, xhi, xlo, 8388608);

    for (int l = 0; l < 2; l++){
        gemm_mma_kernel<<<dim3(16, 512, 2), 256, gemm_smem>>>(l, bxh_f, bhh_f, bxh_b, bhh_b);
        zero_h_kernel<<<512, 256>>>();
        recur_kernel<<<128, 256, REC_SMEM>>>(l, Whh_f, Whh_b, out);
    }
}